// round 13
// baseline (speedup 1.0000x reference)
#include <cuda_runtime.h>
#include <cuda_fp16.h>
#include <cstdint>
#include <math.h>

#define NB 2
#define NC 256
#define NH 128
#define NW 512
#define KC 64
#define NCHUNK (NC / KC)      // 4
#define TM 64                 // w1 rows per tile
#define TN 256                // w2 cols per tile (half of NW)
#define NTHREADS 256
#define TILES_PER_CTA 4
#define NTILES (NB * NH * 8 * 2)         // 4096
#define AR 144                // A fp16 row stride bytes (128 data + 16 pad)
#define BR 528                // B fp16 row stride bytes (512 data + 16 pad)

#define A_OFF 0
#define B_OFF (KC * AR)                  // 9216
#define BUFB  (B_OFF + KC * BR)          // 43008
#define PART_OFF (2 * BUFB)              // 86016
#define SMEM_BYTES (PART_OFF + TM * 4 * 3 * 4)  // 89088

#define NROWS (NB * NH * NW)             // 131072

__device__ float4 g_part[NROWS * 2];     // per (row, half): (Z, S, M, pad)

static __device__ __forceinline__ uint32_t s2u(const void* p) {
    uint32_t a;
    asm("{ .reg .u64 t; cvta.to.shared.u64 t, %1; cvt.u32.u64 %0, t; }" : "=r"(a) : "l"(p));
    return a;
}

#define LDSM4T(r, addr) \
    asm volatile("ldmatrix.sync.aligned.m8n8.x4.trans.shared.b16 {%0,%1,%2,%3}, [%4];" \
        : "=r"((r)[0]), "=r"((r)[1]), "=r"((r)[2]), "=r"((r)[3]) : "r"(addr))

#define MMA(acc, a, b0, b1) \
    asm volatile("mma.sync.aligned.m16n8k16.row.col.f32.f16.f16.f32 " \
        "{%0,%1,%2,%3}, {%4,%5,%6,%7}, {%8,%9}, {%0,%1,%2,%3};" \
        : "+f"((acc)[0]), "+f"((acc)[1]), "+f"((acc)[2]), "+f"((acc)[3]) \
        : "r"((a)[0]), "r"((a)[1]), "r"((a)[2]), "r"((a)[3]), "r"(b0), "r"(b1))

static __device__ __forceinline__ uint32_t packh2(float f0, float f1) {
    __half2 p = __floats2half2_rn(f0, f1);
    return *(uint32_t*)&p;
}

__global__ __launch_bounds__(NTHREADS, 2)
void cost_volume_mma(const float* __restrict__ img1, const float* __restrict__ img2)
{
    extern __shared__ char smem[];
    const uint32_t smem_u = s2u(smem);
    const int t = threadIdx.x;
    const int lane = t & 31, wid = t >> 5;
    const int wm = wid & 1, wn = wid >> 1;     // 2x4 warp grid: 32-row band, 64-col slice

    const size_t cstr = (size_t)NH * NW;

    // per-tile pointer/coordinate setup
    auto tile_ptrs = [&](int tile, const float*& sA, const float*& sB,
                         int& w1o, int& w2o, int& bho) {
        const int half = tile & 1;
        const int mt = (tile >> 1) & 7;
        const int bh_ = tile >> 4;
        const int h_ = bh_ & (NH - 1);
        const int b_ = bh_ >> 7;
        w1o = mt * TM; w2o = half * TN; bho = bh_;
        sA = img1 + ((size_t)b_ * NC * NH + h_) * NW + w1o + lane * 2;
        sB = img2 + ((size_t)b_ * NC * NH + h_) * NW + w2o + lane * 4;
    };

    uint2 sB[4][2];
    uint32_t sA[4];

    // stage 4 channels (one half) of a chunk into regs, from explicit sources
    auto stage_half = [&](const float* srcA, const float* srcB, int k0, int hh) {
        #pragma unroll
        for (int j = 0; j < 4; j++) {
            const int cc = hh * 4 + j;
            const size_t kk = (size_t)(k0 + wid + cc * 8) * cstr;
            float4 v0 = __ldg((const float4*)(srcB + kk));
            float4 v1 = __ldg((const float4*)(srcB + kk + 128));
            sB[j][0] = make_uint2(packh2(v0.x, v0.y), packh2(v0.z, v0.w));
            sB[j][1] = make_uint2(packh2(v1.x, v1.y), packh2(v1.z, v1.w));
            float2 a = __ldg((const float2*)(srcA + kk));
            sA[j] = packh2(a.x, a.y);
        }
    };
    auto store_half = [&](char* bb, int hh) {
        #pragma unroll
        for (int j = 0; j < 4; j++) {
            const int ch = wid + (hh * 4 + j) * 8;
            *(uint2*)(bb + B_OFF + ch * BR + lane * 8)       = sB[j][0];
            *(uint2*)(bb + B_OFF + ch * BR + lane * 8 + 256) = sB[j][1];
            *(uint32_t*)(bb + A_OFF + ch * AR + lane * 4)    = sA[j];
        }
    };

    // trans-LDSM lane mapping
    const int klane = (lane & 7) + ((lane >> 4) << 3);
    const int wblk = ((lane >> 3) & 1) << 3;
    const uint32_t a0off = (uint32_t)klane * AR + (uint32_t)(wm * 32 + wblk) * 2;
    const uint32_t boff  = (uint32_t)klane * BR + (uint32_t)(wn * 64 + wblk) * 2;

    // current / next tile state
    int tile0 = blockIdx.x * TILES_PER_CTA;
    const float *srcA, *srcB, *srcA_n, *srcB_n;
    int w1_0, w2_0, bh, w1n, w2n, bhn;
    tile_ptrs(tile0, srcA, srcB, w1_0, w2_0, bh);

    // ---- global prologue: tile0 chunk0 ----
    stage_half(srcA, srcB, 0, 0); store_half(smem, 0);
    stage_half(srcA, srcB, 0, 1); store_half(smem, 1);
    __syncthreads();

    int gchunk = 0;   // global chunk counter (buffer parity)
    const float scale = 0.0625f;   // 1/sqrt(256)
    float* part = (float*)(smem + PART_OFF);   // [64 rows][4 wn][3]

    for (int it = 0; it < TILES_PER_CTA; it++) {
        const int ntile = (it + 1 < TILES_PER_CTA) ? (tile0 + it + 1) : (tile0 + it);
        tile_ptrs(ntile, srcA_n, srcB_n, w1n, w2n, bhn);
        const bool last_tile = (it + 1 == TILES_PER_CTA);

        float acc[64];                         // [m2][g4][n2][4]
        #pragma unroll
        for (int i = 0; i < 64; i++) acc[i] = 0.f;

        for (int chunk = 0; chunk < NCHUNK; chunk++) {
            const uint32_t base = smem_u + (uint32_t)(gchunk & 1) * BUFB;
            char* nbb = smem + ((gchunk + 1) & 1) * BUFB;
            const bool more = !(last_tile && chunk == NCHUNK - 1);
            const bool intile = (chunk + 1 < NCHUNK);
            const float* nsA = intile ? srcA : srcA_n;
            const float* nsB = intile ? srcB : srcB_n;
            const int nk0 = intile ? (chunk + 1) * KC : 0;

            if (more) stage_half(nsA, nsB, nk0, 0);

            #pragma unroll
            for (int kg = 0; kg < 4; kg++) {               // four K=16 groups
                if (kg == 2 && more) {                     // mid-chunk: drain half0, launch half1
                    store_half(nbb, 0);
                    stage_half(nsA, nsB, nk0, 1);
                }
                const uint32_t ka = base + A_OFF + kg * 16 * AR + a0off;
                const uint32_t kb = base + B_OFF + kg * 16 * BR + boff;
                uint32_t A0[4], A1[4];
                LDSM4T(A0, ka);
                LDSM4T(A1, ka + 32);                       // +16 rows of w1
                #pragma unroll
                for (int g = 0; g < 4; g++) {
                    uint32_t Bg[4];
                    LDSM4T(Bg, kb + g * 32);
                    float* a00 = acc + ((0 * 4 + g) * 2 + 0) * 4;
                    float* a01 = acc + ((0 * 4 + g) * 2 + 1) * 4;
                    float* a10 = acc + ((1 * 4 + g) * 2 + 0) * 4;
                    float* a11 = acc + ((1 * 4 + g) * 2 + 1) * 4;
                    MMA(a00, A0, Bg[0], Bg[2]);
                    MMA(a01, A0, Bg[1], Bg[3]);
                    MMA(a10, A1, Bg[0], Bg[2]);
                    MMA(a11, A1, Bg[1], Bg[3]);
                }
            }

            if (more) store_half(nbb, 1);
            __syncthreads();
            gchunk++;
        }

        // ---- epilogue for this tile (next tile's chunk0 already staged in smem) ----
        #pragma unroll
        for (int m = 0; m < 2; m++) {
            const int r0 = wm * 32 + m * 16 + (lane >> 2);   // rows r0, r0+8
            const int w1g0 = w1_0 + r0, w1g1 = w1g0 + 8;
            float Z0 = 0.f, S0 = 0.f, M0 = 0.f, Z1 = 0.f, S1 = 0.f, M1 = 0.f;
            #pragma unroll
            for (int g = 0; g < 4; g++)
                #pragma unroll
                for (int n = 0; n < 2; n++) {
                    const float* a = acc + ((m * 4 + g) * 2 + n) * 4;
                    const int c0 = w2_0 + wn * 64 + g * 16 + n * 8 + (lane & 3) * 2;
                    float e;
                    e = __expf(a[0] * scale); Z0 += e;
                    if (c0     <= w1g0) { S0 += e * (float)c0;       M0 = fmaxf(M0, e); }
                    e = __expf(a[1] * scale); Z0 += e;
                    if (c0 + 1 <= w1g0) { S0 += e * (float)(c0 + 1); M0 = fmaxf(M0, e); }
                    e = __expf(a[2] * scale); Z1 += e;
                    if (c0     <= w1g1) { S1 += e * (float)c0;       M1 = fmaxf(M1, e); }
                    e = __expf(a[3] * scale); Z1 += e;
                    if (c0 + 1 <= w1g1) { S1 += e * (float)(c0 + 1); M1 = fmaxf(M1, e); }
                }
            #pragma unroll
            for (int off = 1; off <= 2; off <<= 1) {
                Z0 += __shfl_xor_sync(0xffffffffu, Z0, off);
                S0 += __shfl_xor_sync(0xffffffffu, S0, off);
                M0 = fmaxf(M0, __shfl_xor_sync(0xffffffffu, M0, off));
                Z1 += __shfl_xor_sync(0xffffffffu, Z1, off);
                S1 += __shfl_xor_sync(0xffffffffu, S1, off);
                M1 = fmaxf(M1, __shfl_xor_sync(0xffffffffu, M1, off));
            }
            if ((lane & 3) == 0) {
                int i0 = (r0 * 4 + wn) * 3, i1 = ((r0 + 8) * 4 + wn) * 3;
                part[i0] = Z0; part[i0+1] = S0; part[i0+2] = M0;
                part[i1] = Z1; part[i1+1] = S1; part[i1+2] = M1;
            }
        }
        __syncthreads();

        if (t < TM) {
            float Zt = 0.f, St = 0.f, Mt = 0.f;
            #pragma unroll
            for (int g = 0; g < 4; g++) {
                const int q = (t * 4 + g) * 3;
                Zt += part[q]; St += part[q+1]; Mt = fmaxf(Mt, part[q+2]);
            }
            const int half = (tile0 + it) & 1;
            g_part[(size_t)(bh * NW + w1_0 + t) * 2 + half] = make_float4(Zt, St, Mt, 0.f);
        }
        __syncthreads();   // part[] reusable next tile

        srcA = srcA_n; srcB = srcB_n;
        w1_0 = w1n; w2_0 = w2n; bh = bhn;
    }
}

__global__ __launch_bounds__(256)
void combine_kernel(const float* __restrict__ intri1, const float* __restrict__ extri1,
                    const float* __restrict__ extri2, float* __restrict__ out, int nout)
{
    const int i = blockIdx.x * 256 + threadIdx.x;    // over NB*NH*NW rows
    if (i >= NROWS) return;
    const int w1 = i & (NW - 1);
    const int bh = i >> 9;
    const int b = bh >> 7;

    const float4 p0 = g_part[(size_t)i * 2];
    const float4 p1 = g_part[(size_t)i * 2 + 1];
    const float Z = p0.x + p1.x;
    const float S = p0.y + p1.y;
    const float M = fmaxf(p0.z, p1.z);

    const float fx = __ldg(intri1 + b * 9);
    const float dx = __ldg(extri1 + b * 16 + 3)  - __ldg(extri2 + b * 16 + 3);
    const float dy = __ldg(extri1 + b * 16 + 7)  - __ldg(extri2 + b * 16 + 7);
    const float dz = __ldg(extri1 + b * 16 + 11) - __ldg(extri2 + b * 16 + 11);
    const float fb = fx * sqrtf(dx * dx + dy * dy + dz * dz);

    const float inv = 1.f / Z;
    const float corresp = S * inv;
    const float conf = M * inv;
    float disp = fmaxf(fabsf(corresp - (float)w1) * (1.0f / NW), 0.1f);
    out[i] = fb / disp;
    out[nout + i] = conf;
}

extern "C" void kernel_launch(void* const* d_in, const int* in_sizes, int n_in,
                              void* d_out, int out_size) {
    const float* img1   = (const float*)d_in[0];
    const float* img2   = (const float*)d_in[1];
    const float* intri1 = (const float*)d_in[2];
    const float* extri1 = (const float*)d_in[4];
    const float* extri2 = (const float*)d_in[5];
    float* out = (float*)d_out;
    const int nout = out_size / 2;

    cudaFuncSetAttribute(cost_volume_mma,
                         cudaFuncAttributeMaxDynamicSharedMemorySize, SMEM_BYTES);
    dim3 grid(NTILES / TILES_PER_CTA);   // 1024 CTAs x 4 tiles
    cost_volume_mma<<<grid, NTHREADS, SMEM_BYTES>>>(img1, img2);
    combine_kernel<<<(NROWS + 255) / 256, 256>>>(intri1, extri1, extri2, out, nout);
}

// round 14
// speedup vs baseline: 1.1564x; 1.1564x over previous
#include <cuda_runtime.h>
#include <cuda_fp16.h>
#include <cstdint>
#include <math.h>

#define NB 2
#define NC 256
#define NH 128
#define NW 512
#define KC 64
#define NCHUNK (NC / KC)      // 4
#define TM 64                 // w1 rows per CTA
#define TN 256                // w2 cols per CTA (half of NW)
#define NTHREADS 256
#define AR 144                // A fp16 row stride bytes (128 data + 16 pad)
#define BR 528                // B fp16 row stride bytes (512 data + 16 pad)

#define A_OFF 0
#define B_OFF (KC * AR)                  // 9216
#define BUFB  (B_OFF + KC * BR)          // 43008
#define PART_OFF (2 * BUFB)              // 86016
#define SMEM_BYTES (PART_OFF + TM * 4 * 3 * 4)  // 89088

#define NROWS (NB * NH * NW)             // 131072

__device__ float4 g_part[NROWS * 2];     // per (row, half): (Z, S, M, pad)

static __device__ __forceinline__ uint32_t s2u(const void* p) {
    uint32_t a;
    asm("{ .reg .u64 t; cvta.to.shared.u64 t, %1; cvt.u32.u64 %0, t; }" : "=r"(a) : "l"(p));
    return a;
}

#define LDSM4T(r, addr) \
    asm volatile("ldmatrix.sync.aligned.m8n8.x4.trans.shared.b16 {%0,%1,%2,%3}, [%4];" \
        : "=r"((r)[0]), "=r"((r)[1]), "=r"((r)[2]), "=r"((r)[3]) : "r"(addr))

#define MMA(acc, a, b0, b1) \
    asm volatile("mma.sync.aligned.m16n8k16.row.col.f32.f16.f16.f32 " \
        "{%0,%1,%2,%3}, {%4,%5,%6,%7}, {%8,%9}, {%0,%1,%2,%3};" \
        : "+f"((acc)[0]), "+f"((acc)[1]), "+f"((acc)[2]), "+f"((acc)[3]) \
        : "r"((a)[0]), "r"((a)[1]), "r"((a)[2]), "r"((a)[3]), "r"(b0), "r"(b1))

static __device__ __forceinline__ uint32_t packh2(float f0, float f1) {
    __half2 p = __floats2half2_rn(f0, f1);
    return *(uint32_t*)&p;
}

__global__ __launch_bounds__(NTHREADS, 2)
void cost_volume_mma(const float* __restrict__ img1, const float* __restrict__ img2)
{
    extern __shared__ char smem[];
    const uint32_t smem_u = s2u(smem);
    const int t = threadIdx.x;
    const int lane = t & 31, wid = t >> 5;
    const int wm = wid & 1, wn = wid >> 1;     // 2x4 warp grid: 32-row band, 64-col slice

    const int cta = blockIdx.x;                // bh*16 + mtile*2 + half
    const int half = cta & 1;
    const int mtile = (cta >> 1) & 7;
    const int bh = cta >> 4;
    const int h = bh & (NH - 1);
    const int b = bh >> 7;
    const int w1_0 = mtile * TM;
    const int w2_0 = half * TN;

    const size_t cstr = (size_t)NH * NW;
    const float* g1 = img1 + ((size_t)b * NC * NH + h) * NW + w1_0;
    const float* g2 = img2 + ((size_t)b * NC * NH + h) * NW + w2_0;

    const float* srcA = g1 + lane * 2;
    const float* srcB = g2 + lane * 4;

    float acc[64];                             // [m2][g4][n2][4]
    #pragma unroll
    for (int i = 0; i < 64; i++) acc[i] = 0.f;

    uint2 sB[4][2];
    uint32_t sA[4];

    auto stage_half = [&](int k0, int hh) {
        #pragma unroll
        for (int j = 0; j < 4; j++) {
            const int cc = hh * 4 + j;
            const size_t kk = (size_t)(k0 + wid + cc * 8) * cstr;
            float4 v0 = __ldg((const float4*)(srcB + kk));
            float4 v1 = __ldg((const float4*)(srcB + kk + 128));
            sB[j][0] = make_uint2(packh2(v0.x, v0.y), packh2(v0.z, v0.w));
            sB[j][1] = make_uint2(packh2(v1.x, v1.y), packh2(v1.z, v1.w));
            float2 a = __ldg((const float2*)(srcA + kk));
            sA[j] = packh2(a.x, a.y);
        }
    };
    auto store_half = [&](char* bb, int hh) {
        #pragma unroll
        for (int j = 0; j < 4; j++) {
            const int ch = wid + (hh * 4 + j) * 8;
            *(uint2*)(bb + B_OFF + ch * BR + lane * 8)       = sB[j][0];
            *(uint2*)(bb + B_OFF + ch * BR + lane * 8 + 256) = sB[j][1];
            *(uint32_t*)(bb + A_OFF + ch * AR + lane * 4)    = sA[j];
        }
    };

    // ---- prologue: chunk 0 ----
    stage_half(0, 0); store_half(smem, 0);
    stage_half(0, 1); store_half(smem, 1);
    __syncthreads();

    // trans-LDSM lane mapping: k = (lane&7) + 8*(lane>>4), wblk = 8*((lane>>3)&1)
    const int klane = (lane & 7) + ((lane >> 4) << 3);
    const int wblk = ((lane >> 3) & 1) << 3;
    const uint32_t a0off = (uint32_t)klane * AR + (uint32_t)(wm * 32 + wblk) * 2;
    const uint32_t boff  = (uint32_t)klane * BR + (uint32_t)(wn * 64 + wblk) * 2;

    for (int chunk = 0; chunk < NCHUNK; chunk++) {
        const uint32_t base = smem_u + (uint32_t)(chunk & 1) * BUFB;
        char* nbb = smem + ((chunk + 1) & 1) * BUFB;
        const bool more = (chunk + 1 < NCHUNK);

        if (more) stage_half((chunk + 1) * KC, 0);

        #pragma unroll
        for (int kg = 0; kg < 4; kg++) {                   // four K=16 groups
            if (kg == 1 && more) store_half(nbb, 0);       // spread LSU work across kgs
            if (kg == 2 && more) stage_half((chunk + 1) * KC, 1);

            const uint32_t ka = base + A_OFF + kg * 16 * AR + a0off;
            const uint32_t kb = base + B_OFF + kg * 16 * BR + boff;
            uint32_t A0[4], A1[4];
            LDSM4T(A0, ka);
            LDSM4T(A1, ka + 32);                           // +16 rows of w1

            uint32_t Bbuf[2][4];                           // B double buffer
            LDSM4T(Bbuf[0], kb);
            #pragma unroll
            for (int g = 0; g < 4; g++) {
                if (g < 3) LDSM4T(Bbuf[(g + 1) & 1], kb + (g + 1) * 32);
                const uint32_t* Bg = Bbuf[g & 1];
                float* a00 = acc + ((0 * 4 + g) * 2 + 0) * 4;
                float* a01 = acc + ((0 * 4 + g) * 2 + 1) * 4;
                float* a10 = acc + ((1 * 4 + g) * 2 + 0) * 4;
                float* a11 = acc + ((1 * 4 + g) * 2 + 1) * 4;
                MMA(a00, A0, Bg[0], Bg[2]);
                MMA(a01, A0, Bg[1], Bg[3]);
                MMA(a10, A1, Bg[0], Bg[2]);
                MMA(a11, A1, Bg[1], Bg[3]);
            }
        }

        if (more) store_half(nbb, 1);
        __syncthreads();
    }

    // ---- epilogue: partial softmax stats over this CTA's 256 cols ----
    const float scale = 0.0625f;   // 1/sqrt(256)
    float* part = (float*)(smem + PART_OFF);   // [64 rows][4 wn][3]
    #pragma unroll
    for (int m = 0; m < 2; m++) {
        const int r0 = wm * 32 + m * 16 + (lane >> 2);   // rows r0, r0+8
        const int w1g0 = w1_0 + r0, w1g1 = w1g0 + 8;
        float Z0 = 0.f, S0 = 0.f, M0 = 0.f, Z1 = 0.f, S1 = 0.f, M1 = 0.f;
        #pragma unroll
        for (int g = 0; g < 4; g++)
            #pragma unroll
            for (int n = 0; n < 2; n++) {
                const float* a = acc + ((m * 4 + g) * 2 + n) * 4;
                const int c0 = w2_0 + wn * 64 + g * 16 + n * 8 + (lane & 3) * 2;
                float e;
                e = __expf(a[0] * scale); Z0 += e;
                if (c0     <= w1g0) { S0 += e * (float)c0;       M0 = fmaxf(M0, e); }
                e = __expf(a[1] * scale); Z0 += e;
                if (c0 + 1 <= w1g0) { S0 += e * (float)(c0 + 1); M0 = fmaxf(M0, e); }
                e = __expf(a[2] * scale); Z1 += e;
                if (c0     <= w1g1) { S1 += e * (float)c0;       M1 = fmaxf(M1, e); }
                e = __expf(a[3] * scale); Z1 += e;
                if (c0 + 1 <= w1g1) { S1 += e * (float)(c0 + 1); M1 = fmaxf(M1, e); }
            }
        #pragma unroll
        for (int off = 1; off <= 2; off <<= 1) {
            Z0 += __shfl_xor_sync(0xffffffffu, Z0, off);
            S0 += __shfl_xor_sync(0xffffffffu, S0, off);
            M0 = fmaxf(M0, __shfl_xor_sync(0xffffffffu, M0, off));
            Z1 += __shfl_xor_sync(0xffffffffu, Z1, off);
            S1 += __shfl_xor_sync(0xffffffffu, S1, off);
            M1 = fmaxf(M1, __shfl_xor_sync(0xffffffffu, M1, off));
        }
        if ((lane & 3) == 0) {
            int i0 = (r0 * 4 + wn) * 3, i1 = ((r0 + 8) * 4 + wn) * 3;
            part[i0] = Z0; part[i0+1] = S0; part[i0+2] = M0;
            part[i1] = Z1; part[i1+1] = S1; part[i1+2] = M1;
        }
    }
    __syncthreads();

    if (t < TM) {
        float Zt = 0.f, St = 0.f, Mt = 0.f;
        #pragma unroll
        for (int g = 0; g < 4; g++) {
            const int q = (t * 4 + g) * 3;
            Zt += part[q]; St += part[q+1]; Mt = fmaxf(Mt, part[q+2]);
        }
        g_part[(size_t)(bh * NW + w1_0 + t) * 2 + half] = make_float4(Zt, St, Mt, 0.f);
    }
}

__global__ __launch_bounds__(256)
void combine_kernel(const float* __restrict__ intri1, const float* __restrict__ extri1,
                    const float* __restrict__ extri2, float* __restrict__ out, int nout)
{
    const int i = blockIdx.x * 256 + threadIdx.x;    // over NB*NH*NW rows
    if (i >= NROWS) return;
    const int w1 = i & (NW - 1);
    const int bh = i >> 9;
    const int b = bh >> 7;

    const float4 p0 = g_part[(size_t)i * 2];
    const float4 p1 = g_part[(size_t)i * 2 + 1];
    const float Z = p0.x + p1.x;
    const float S = p0.y + p1.y;
    const float M = fmaxf(p0.z, p1.z);

    const float fx = __ldg(intri1 + b * 9);
    const float dx = __ldg(extri1 + b * 16 + 3)  - __ldg(extri2 + b * 16 + 3);
    const float dy = __ldg(extri1 + b * 16 + 7)  - __ldg(extri2 + b * 16 + 7);
    const float dz = __ldg(extri1 + b * 16 + 11) - __ldg(extri2 + b * 16 + 11);
    const float fb = fx * sqrtf(dx * dx + dy * dy + dz * dz);

    const float inv = 1.f / Z;
    const float corresp = S * inv;
    const float conf = M * inv;
    float disp = fmaxf(fabsf(corresp - (float)w1) * (1.0f / NW), 0.1f);
    out[i] = fb / disp;
    out[nout + i] = conf;
}

extern "C" void kernel_launch(void* const* d_in, const int* in_sizes, int n_in,
                              void* d_out, int out_size) {
    const float* img1   = (const float*)d_in[0];
    const float* img2   = (const float*)d_in[1];
    const float* intri1 = (const float*)d_in[2];
    const float* extri1 = (const float*)d_in[4];
    const float* extri2 = (const float*)d_in[5];
    float* out = (float*)d_out;
    const int nout = out_size / 2;

    cudaFuncSetAttribute(cost_volume_mma,
                         cudaFuncAttributeMaxDynamicSharedMemorySize, SMEM_BYTES);
    dim3 grid(NB * NH * 8 * 2);   // 4096 CTAs (8 m-tiles x 2 halves per bh)
    cost_volume_mma<<<grid, NTHREADS, SMEM_BYTES>>>(img1, img2);
    combine_kernel<<<(NROWS + 255) / 256, 256>>>(intri1, extri1, extri2, out, nout);
}

// round 15
// speedup vs baseline: 1.2736x; 1.1013x over previous
#include <cuda_runtime.h>
#include <cuda_fp16.h>
#include <cstdint>
#include <math.h>

#define NB 2
#define NC 256
#define NH 128
#define NW 512
#define KC 32
#define NCHUNK (NC / KC)      // 8
#define TM 64                 // w1 rows per CTA
#define TN 256                // w2 cols per CTA (half of NW)
#define NTHREADS 256
#define AR 144                // A fp16 row stride bytes (128 data + 16 pad)
#define BR 528                // B fp16 row stride bytes (512 data + 16 pad)

#define A_OFF 0
#define B_OFF (KC * AR)                  // 4608
#define STAGEB (B_OFF + KC * BR)         // 21504
#define PART_OFF (3 * STAGEB)            // 64512
#define SMEM_BYTES (PART_OFF + TM * 4 * 3 * 4)  // 67584

#define NROWS (NB * NH * NW)             // 131072
#define NELEM2 (NB * NC * NH * NW)       // 33554432 img2 elements

__device__ float4 g_part[NROWS * 2];                 // per (row, half): (Z, S, M)
__device__ __align__(16) uint4 g_img2h4[NELEM2 / 8]; // img2 as fp16, 16B-aligned

static __device__ __forceinline__ uint32_t s2u(const void* p) {
    uint32_t a;
    asm("{ .reg .u64 t; cvta.to.shared.u64 t, %1; cvt.u32.u64 %0, t; }" : "=r"(a) : "l"(p));
    return a;
}

#define LDSM4T(r, addr) \
    asm volatile("ldmatrix.sync.aligned.m8n8.x4.trans.shared.b16 {%0,%1,%2,%3}, [%4];" \
        : "=r"((r)[0]), "=r"((r)[1]), "=r"((r)[2]), "=r"((r)[3]) : "r"(addr))

#define MMA(acc, a, b0, b1) \
    asm volatile("mma.sync.aligned.m16n8k16.row.col.f32.f16.f16.f32 " \
        "{%0,%1,%2,%3}, {%4,%5,%6,%7}, {%8,%9}, {%0,%1,%2,%3};" \
        : "+f"((acc)[0]), "+f"((acc)[1]), "+f"((acc)[2]), "+f"((acc)[3]) \
        : "r"((a)[0]), "r"((a)[1]), "r"((a)[2]), "r"((a)[3]), "r"(b0), "r"(b1))

#define CPA16(dst, src) \
    asm volatile("cp.async.cg.shared.global [%0], [%1], 16;" :: "r"(dst), "l"(src))
#define CP_COMMIT() asm volatile("cp.async.commit_group;")

static __device__ __forceinline__ uint32_t packh2(float f0, float f1) {
    __half2 p = __floats2half2_rn(f0, f1);
    return *(uint32_t*)&p;
}

// ---- kernel 1: img2 fp32 -> fp16 (rn), done once ----
__global__ __launch_bounds__(256)
void convert_kernel(const float* __restrict__ img2)
{
    const int gid = blockIdx.x * 1024 + threadIdx.x;   // 8192 blocks
    uint2* dst = (uint2*)g_img2h4;
    #pragma unroll
    for (int j = 0; j < 4; j++) {
        const int i = gid + j * 256;
        float4 v = __ldg((const float4*)img2 + i);
        dst[i] = make_uint2(packh2(v.x, v.y), packh2(v.z, v.w));
    }
}

// ---- kernel 2: GEMM + partial softmax ----
__global__ __launch_bounds__(NTHREADS, 2)
void cost_volume_mma(const float* __restrict__ img1)
{
    extern __shared__ char smem[];
    const uint32_t smem_u = s2u(smem);
    const int t = threadIdx.x;
    const int lane = t & 31, wid = t >> 5;
    const int wm = wid & 1, wn = wid >> 1;     // 2x4 warp grid

    const int cta = blockIdx.x;                // bh*16 + mtile*2 + half
    const int half = cta & 1;
    const int mtile = (cta >> 1) & 7;
    const int bh = cta >> 4;
    const int h = bh & (NH - 1);
    const int b = bh >> 7;
    const int w1_0 = mtile * TM;
    const int w2_0 = half * TN;

    const size_t cstr = (size_t)NH * NW;
    const float*  g1 = img1 + ((size_t)b * NC * NH + h) * NW + w1_0;
    const __half* g2 = (const __half*)g_img2h4 + ((size_t)b * NC * NH + h) * NW + w2_0;

    // B cp.async mapping: seg = t&31 (16B col segment), rowbase = t>>5, rows +8j
    const int segB = t & 31, rowB = t >> 5;
    const __half* srcB = g2 + segB * 8;
    // A staging: warp wid owns channels {k0 + wid + 8j}; col = lane*2
    const float* srcA = g1 + lane * 2;

    float acc[64];                             // [m2][g4][n2][4]
    #pragma unroll
    for (int i = 0; i < 64; i++) acc[i] = 0.f;

    uint32_t sA[4];

    auto issueB = [&](int k0, uint32_t bufu) {
        #pragma unroll
        for (int j = 0; j < 4; j++) {
            const int row = rowB + j * 8;
            CPA16(bufu + B_OFF + row * BR + segB * 16,
                  srcB + (size_t)(k0 + row) * cstr);
        }
        CP_COMMIT();
    };
    auto ldgA = [&](int k0) {
        #pragma unroll
        for (int j = 0; j < 4; j++) {
            float2 a = __ldg((const float2*)(srcA + (size_t)(k0 + wid + j * 8) * cstr));
            sA[j] = packh2(a.x, a.y);
        }
    };
    auto storeA = [&](uint32_t bufu) {
        #pragma unroll
        for (int j = 0; j < 4; j++)
            *(uint32_t*)(smem + (bufu - smem_u) + A_OFF + (wid + j * 8) * AR + lane * 4) = sA[j];
    };

    const uint32_t buf[3] = { smem_u, smem_u + STAGEB, smem_u + 2 * STAGEB };

    // ---- prologue: fill stages 0 and 1 ----
    ldgA(0);      storeA(buf[0]);
    ldgA(KC);     storeA(buf[1]);
    issueB(0, buf[0]);
    issueB(KC, buf[1]);

    // trans-LDSM lane mapping
    const int klane = (lane & 7) + ((lane >> 4) << 3);
    const int wblk = ((lane >> 3) & 1) << 3;
    const uint32_t a0off = (uint32_t)klane * AR + (uint32_t)(wm * 32 + wblk) * 2;
    const uint32_t boff  = (uint32_t)klane * BR + (uint32_t)(wn * 64 + wblk) * 2;

    for (int c = 0; c < NCHUNK; c++) {
        if (c >= NCHUNK - 2)
            asm volatile("cp.async.wait_group 0;" ::: "memory");
        else
            asm volatile("cp.async.wait_group 1;" ::: "memory");
        __syncthreads();   // chunk c data visible; buffer (c+2)%3 free

        const bool more = (c + 2 < NCHUNK);
        if (more) {
            issueB((c + 2) * KC, buf[(c + 2) % 3]);
            ldgA((c + 2) * KC);
        }

        // ---- compute chunk c ----
        const uint32_t base = buf[c % 3];
        #pragma unroll
        for (int kg = 0; kg < 2; kg++) {
            const uint32_t ka = base + A_OFF + kg * 16 * AR + a0off;
            const uint32_t kb = base + B_OFF + kg * 16 * BR + boff;
            uint32_t A0[4], A1[4];
            LDSM4T(A0, ka);
            LDSM4T(A1, ka + 32);
            uint32_t Bbuf[2][4];
            LDSM4T(Bbuf[0], kb);
            #pragma unroll
            for (int g = 0; g < 4; g++) {
                if (g < 3) LDSM4T(Bbuf[(g + 1) & 1], kb + (g + 1) * 32);
                const uint32_t* Bg = Bbuf[g & 1];
                float* a00 = acc + ((0 * 4 + g) * 2 + 0) * 4;
                float* a01 = acc + ((0 * 4 + g) * 2 + 1) * 4;
                float* a10 = acc + ((1 * 4 + g) * 2 + 0) * 4;
                float* a11 = acc + ((1 * 4 + g) * 2 + 1) * 4;
                MMA(a00, A0, Bg[0], Bg[2]);
                MMA(a01, A0, Bg[1], Bg[3]);
                MMA(a10, A1, Bg[0], Bg[2]);
                MMA(a11, A1, Bg[1], Bg[3]);
            }
        }

        if (more) storeA(buf[(c + 2) % 3]);
    }

    // ---- epilogue: partial softmax stats over this CTA's 256 cols ----
    const float scale = 0.0625f;   // 1/sqrt(256)
    float* part = (float*)(smem + PART_OFF);   // [64 rows][4 wn][3]
    #pragma unroll
    for (int m = 0; m < 2; m++) {
        const int r0 = wm * 32 + m * 16 + (lane >> 2);
        const int w1g0 = w1_0 + r0, w1g1 = w1g0 + 8;
        float Z0 = 0.f, S0 = 0.f, M0 = 0.f, Z1 = 0.f, S1 = 0.f, M1 = 0.f;
        #pragma unroll
        for (int g = 0; g < 4; g++)
            #pragma unroll
            for (int n = 0; n < 2; n++) {
                const float* a = acc + ((m * 4 + g) * 2 + n) * 4;
                const int c0 = w2_0 + wn * 64 + g * 16 + n * 8 + (lane & 3) * 2;
                float e;
                e = __expf(a[0] * scale); Z0 += e;
                if (c0     <= w1g0) { S0 += e * (float)c0;       M0 = fmaxf(M0, e); }
                e = __expf(a[1] * scale); Z0 += e;
                if (c0 + 1 <= w1g0) { S0 += e * (float)(c0 + 1); M0 = fmaxf(M0, e); }
                e = __expf(a[2] * scale); Z1 += e;
                if (c0     <= w1g1) { S1 += e * (float)c0;       M1 = fmaxf(M1, e); }
                e = __expf(a[3] * scale); Z1 += e;
                if (c0 + 1 <= w1g1) { S1 += e * (float)(c0 + 1); M1 = fmaxf(M1, e); }
            }
        #pragma unroll
        for (int off = 1; off <= 2; off <<= 1) {
            Z0 += __shfl_xor_sync(0xffffffffu, Z0, off);
            S0 += __shfl_xor_sync(0xffffffffu, S0, off);
            M0 = fmaxf(M0, __shfl_xor_sync(0xffffffffu, M0, off));
            Z1 += __shfl_xor_sync(0xffffffffu, Z1, off);
            S1 += __shfl_xor_sync(0xffffffffu, S1, off);
            M1 = fmaxf(M1, __shfl_xor_sync(0xffffffffu, M1, off));
        }
        if ((lane & 3) == 0) {
            int i0 = (r0 * 4 + wn) * 3, i1 = ((r0 + 8) * 4 + wn) * 3;
            part[i0] = Z0; part[i0+1] = S0; part[i0+2] = M0;
            part[i1] = Z1; part[i1+1] = S1; part[i1+2] = M1;
        }
    }
    __syncthreads();

    if (t < TM) {
        float Zt = 0.f, St = 0.f, Mt = 0.f;
        #pragma unroll
        for (int g = 0; g < 4; g++) {
            const int q = (t * 4 + g) * 3;
            Zt += part[q]; St += part[q+1]; Mt = fmaxf(Mt, part[q+2]);
        }
        g_part[(size_t)(bh * NW + w1_0 + t) * 2 + half] = make_float4(Zt, St, Mt, 0.f);
    }
}

__global__ __launch_bounds__(256)
void combine_kernel(const float* __restrict__ intri1, const float* __restrict__ extri1,
                    const float* __restrict__ extri2, float* __restrict__ out, int nout)
{
    const int i = blockIdx.x * 256 + threadIdx.x;
    if (i >= NROWS) return;
    const int w1 = i & (NW - 1);
    const int bh = i >> 9;
    const int b = bh >> 7;

    const float4 p0 = g_part[(size_t)i * 2];
    const float4 p1 = g_part[(size_t)i * 2 + 1];
    const float Z = p0.x + p1.x;
    const float S = p0.y + p1.y;
    const float M = fmaxf(p0.z, p1.z);

    const float fx = __ldg(intri1 + b * 9);
    const float dx = __ldg(extri1 + b * 16 + 3)  - __ldg(extri2 + b * 16 + 3);
    const float dy = __ldg(extri1 + b * 16 + 7)  - __ldg(extri2 + b * 16 + 7);
    const float dz = __ldg(extri1 + b * 16 + 11) - __ldg(extri2 + b * 16 + 11);
    const float fb = fx * sqrtf(dx * dx + dy * dy + dz * dz);

    const float inv = 1.f / Z;
    const float corresp = S * inv;
    const float conf = M * inv;
    float disp = fmaxf(fabsf(corresp - (float)w1) * (1.0f / NW), 0.1f);
    out[i] = fb / disp;
    out[nout + i] = conf;
}

extern "C" void kernel_launch(void* const* d_in, const int* in_sizes, int n_in,
                              void* d_out, int out_size) {
    const float* img1   = (const float*)d_in[0];
    const float* img2   = (const float*)d_in[1];
    const float* intri1 = (const float*)d_in[2];
    const float* extri1 = (const float*)d_in[4];
    const float* extri2 = (const float*)d_in[5];
    float* out = (float*)d_out;
    const int nout = out_size / 2;

    convert_kernel<<<NELEM2 / 4096, 256>>>(img2);
    cudaFuncSetAttribute(cost_volume_mma,
                         cudaFuncAttributeMaxDynamicSharedMemorySize, SMEM_BYTES);
    cost_volume_mma<<<NB * NH * 8 * 2, NTHREADS, SMEM_BYTES>>>(img1);
    combine_kernel<<<(NROWS + 255) / 256, 256>>>(intri1, extri1, extri2, out, nout);
}